// round 4
// baseline (speedup 1.0000x reference)
#include <cuda_runtime.h>
#include <cuda_bf16.h>

// PathSampling: per node, score 32 masked paths by summed centrality,
// select top-8 (stable: smaller path index wins ties, matching jax.lax.top_k),
// emit masked paths [n,8,8] then edge rows [n,8,7] as FLOAT32 into d_out.
//
// Layout: one warp per node, lane = candidate path index (0..31).
// Path row (8 int32 = 32B) loaded as 2x int4 -> warp reads 1024B coalesced.
// Rank via 32 shfl broadcasts; lanes with rank<8 self-select and write.

__global__ __launch_bounds__(256) void path_sampling_kernel(
    const int*   __restrict__ paths,      // [n_node, 32, 8]
    const int*   __restrict__ edge_ids,   // [n_node, 32, 7]
    const int*   __restrict__ rand_lens,  // [n_node, 32]
    const float* __restrict__ centrality, // [n_graph]
    float*       __restrict__ out_paths,  // [n_node, 8, 8] float32
    float*       __restrict__ out_edges,  // [n_node, 8, 7] float32
    int n_node)
{
    const int warp_id = (blockIdx.x * blockDim.x + threadIdx.x) >> 5;
    const int lane    = threadIdx.x & 31;
    if (warp_id >= n_node) return;
    const long long node = warp_id;

    // ---- load this lane's path row (coalesced int4 x2) + its length ----
    const int4* prow = reinterpret_cast<const int4*>(paths + (node * 32 + lane) * 8);
    int4 p0 = __ldg(prow + 0);
    int4 p1 = __ldg(prow + 1);
    const int len = __ldg(rand_lens + node * 32 + lane);

    int mp[8] = {p0.x, p0.y, p0.z, p0.w, p1.x, p1.y, p1.z, p1.w};

    // mask (pos > len -> -1) and score (sum centrality over kept positions)
    float score = 0.0f;
#pragma unroll
    for (int j = 0; j < 8; j++) {
        if (j > len) {
            mp[j] = -1;
        } else {
            score += __ldg(centrality + mp[j]);
        }
    }

    // ---- stable rank among 32 lanes: higher score first, tie -> lower lane ----
    int rank = 0;
#pragma unroll
    for (int j = 0; j < 32; j++) {
        float sj = __shfl_sync(0xffffffffu, score, j);
        rank += (sj > score) || (sj == score && j < lane);
    }

    // ---- selected lanes write their rows (as float32 values) at slot = rank ----
    if (rank < 8) {
        float4* op = reinterpret_cast<float4*>(out_paths + (node * 8 + rank) * 8);
        op[0] = make_float4((float)mp[0], (float)mp[1], (float)mp[2], (float)mp[3]);
        op[1] = make_float4((float)mp[4], (float)mp[5], (float)mp[6], (float)mp[7]);

        const int* er = edge_ids + (node * 32 + lane) * 7;
        float*     eo = out_edges + (node * 8 + rank) * 7;
#pragma unroll
        for (int j = 0; j < 7; j++) {
            eo[j] = (float)__ldg(er + j);
        }
    }
}

extern "C" void kernel_launch(void* const* d_in, const int* in_sizes, int n_in,
                              void* d_out, int out_size) {
    // Bind inputs by DESCENDING element count (all distinct, order-agnostic):
    //   1st: paths      25,600,000 (n*32*8)
    //   2nd: edge_ids   22,400,000 (n*32*7)
    //   3rd: rand_lens   3,200,000 (n*32)
    //   4th: centrality    100,000
    //   (size-1 k_path scalar ignored; constant 8)
    int idx[8];
    int m = 0;
    for (int i = 0; i < n_in && m < 8; i++) {
        if (in_sizes[i] > 1) idx[m++] = i;
    }
    for (int a = 1; a < m; a++) {
        int v = idx[a];
        int b = a - 1;
        while (b >= 0 && in_sizes[idx[b]] < in_sizes[v]) { idx[b + 1] = idx[b]; b--; }
        idx[b + 1] = v;
    }

    const int*   paths      = (const int*)  d_in[idx[0]];
    const int*   edge_ids   = (const int*)  d_in[idx[1]];
    const int*   rand_lens  = (const int*)  d_in[idx[2]];
    const float* centrality = (const float*)d_in[idx[3]];

    const int n_node = in_sizes[idx[0]] / (32 * 8);

    float* out_paths = (float*)d_out;                       // [n_node, 8, 8]
    float* out_edges = out_paths + (long long)n_node * 64;  // [n_node, 8, 7]

    const int threads = 256;                  // 8 warps -> 8 nodes per block
    const int blocks  = (n_node + 7) / 8;
    path_sampling_kernel<<<blocks, threads>>>(paths, edge_ids, rand_lens,
                                              centrality, out_paths, out_edges,
                                              n_node);
}

// round 5
// speedup vs baseline: 1.0415x; 1.0415x over previous
#include <cuda_runtime.h>
#include <cuda_bf16.h>

// PathSampling: per node, score 32 masked paths by summed centrality,
// select top-8 (stable: smaller path index wins ties, matching jax.lax.top_k),
// emit masked paths [n,8,8] then edge rows [n,8,7] as FLOAT32 into d_out.
//
// One warp per node, lane = candidate path. Rank via 32 shfl broadcasts.
// Edge rows copied WARP-COOPERATIVELY (2 coalesced passes) instead of
// 7 divergent scalar loads/stores per selected lane.

__global__ __launch_bounds__(256) void path_sampling_kernel(
    const int*   __restrict__ paths,      // [n_node, 32, 8]
    const int*   __restrict__ edge_ids,   // [n_node, 32, 7]
    const int*   __restrict__ rand_lens,  // [n_node, 32]
    const float* __restrict__ centrality, // [n_graph]
    float*       __restrict__ out_paths,  // [n_node, 8, 8] float32
    float*       __restrict__ out_edges,  // [n_node, 8, 7] float32
    int n_node)
{
    const int warp_id = (blockIdx.x * blockDim.x + threadIdx.x) >> 5;
    const int lane    = threadIdx.x & 31;
    if (warp_id >= n_node) return;
    const long long node = warp_id;

    // ---- load this lane's path row (coalesced int4 x2) + its length ----
    const int4* prow = reinterpret_cast<const int4*>(paths + (node * 32 + lane) * 8);
    int4 p0 = __ldg(prow + 0);
    int4 p1 = __ldg(prow + 1);
    const int len = __ldg(rand_lens + node * 32 + lane);

    int mp[8] = {p0.x, p0.y, p0.z, p0.w, p1.x, p1.y, p1.z, p1.w};

    // mask (pos > len -> -1) and score (sum centrality over kept prefix)
    float score = 0.0f;
#pragma unroll
    for (int j = 0; j < 8; j++) {
        if (j > len) {
            mp[j] = -1;
        } else {
            score += __ldg(centrality + mp[j]);
        }
    }

    // ---- stable rank among 32 lanes: higher score first, tie -> lower lane ----
    int rank = 0;
#pragma unroll
    for (int j = 0; j < 32; j++) {
        float sj = __shfl_sync(0xffffffffu, score, j);
        rank += (sj > score) || (sj == score && j < lane);
    }

    // ---- slot -> source lane map: lane r (r<8) holds src lane of rank r ----
    int my_src = 0;
#pragma unroll
    for (int r = 0; r < 8; r++) {
        unsigned mr = __ballot_sync(0xffffffffu, rank == r);
        if (lane == r) my_src = __ffs(mr) - 1;
    }

    // ---- selected lanes write their path row (float32, coalesced 128B) ----
    if (rank < 8) {
        float4* op = reinterpret_cast<float4*>(out_paths + (node * 8 + rank) * 8);
        op[0] = make_float4((float)mp[0], (float)mp[1], (float)mp[2], (float)mp[3]);
        op[1] = make_float4((float)mp[4], (float)mp[5], (float)mp[6], (float)mp[7]);
    }

    // ---- warp-cooperative edge copy: 56 contiguous output floats/node ----
    const int*  ebase = edge_ids + node * (32 * 7);
    float*      obase = out_edges + node * 56;
#pragma unroll
    for (int pass = 0; pass < 2; pass++) {
        int e = lane + pass * 32;          // element 0..63 (active if < 56)
        int s = e / 7;                     // output slot 0..7 (<=9 for inactive)
        int j = e - s * 7;                 // position within row 0..6
        int src = __shfl_sync(0xffffffffu, my_src, s & 7);
        if (e < 56) {
            obase[e] = (float)__ldg(ebase + src * 7 + j);
        }
    }
}

extern "C" void kernel_launch(void* const* d_in, const int* in_sizes, int n_in,
                              void* d_out, int out_size) {
    // Bind inputs by DESCENDING element count (all distinct, order-agnostic):
    //   paths 25.6M (n*32*8) > edge_ids 22.4M (n*32*7) > rand_lens 3.2M (n*32)
    //   > centrality 100K; size-1 k_path scalar ignored (constant 8).
    int idx[8];
    int m = 0;
    for (int i = 0; i < n_in && m < 8; i++) {
        if (in_sizes[i] > 1) idx[m++] = i;
    }
    for (int a = 1; a < m; a++) {
        int v = idx[a];
        int b = a - 1;
        while (b >= 0 && in_sizes[idx[b]] < in_sizes[v]) { idx[b + 1] = idx[b]; b--; }
        idx[b + 1] = v;
    }

    const int*   paths      = (const int*)  d_in[idx[0]];
    const int*   edge_ids   = (const int*)  d_in[idx[1]];
    const int*   rand_lens  = (const int*)  d_in[idx[2]];
    const float* centrality = (const float*)d_in[idx[3]];

    const int n_node = in_sizes[idx[0]] / (32 * 8);

    float* out_paths = (float*)d_out;                       // [n_node, 8, 8]
    float* out_edges = out_paths + (long long)n_node * 64;  // [n_node, 8, 7]

    const int threads = 256;                  // 8 warps -> 8 nodes per block
    const int blocks  = (n_node + 7) / 8;
    path_sampling_kernel<<<blocks, threads>>>(paths, edge_ids, rand_lens,
                                              centrality, out_paths, out_edges,
                                              n_node);
}